// round 7
// baseline (speedup 1.0000x reference)
#include <cuda_runtime.h>

typedef unsigned long long ull;

#define NN 8192
#define DD 128

// Scratch (allocation-free: __device__ globals). q,k stored TRANSPOSED [d][n]
// so the attention kernel's smem tile loads are fully coalesced + conflict-free.
__device__ float g_qt[(size_t)DD * NN];
__device__ float g_kt[(size_t)DD * NN];
__device__ float g_v [(size_t)NN * DD];
__device__ float g_m [(size_t)NN * DD];

// ---- packed f32x2 helpers (FFMA2 path — 2x fp32 throughput on sm_103a) ----
__device__ __forceinline__ ull pk2(float lo, float hi) {
    ull r; asm("mov.b64 %0, {%1,%2};" : "=l"(r) : "f"(lo), "f"(hi)); return r;
}
__device__ __forceinline__ void upk2(ull v, float& lo, float& hi) {
    asm("mov.b64 {%0,%1}, %2;" : "=f"(lo), "=f"(hi) : "l"(v));
}
__device__ __forceinline__ void fma2(ull& d, ull a, ull b) {
    asm("fma.rn.f32x2 %0, %1, %2, %0;" : "+l"(d) : "l"(a), "l"(b));
}
__device__ __forceinline__ ull mul2(ull a, ull b) {
    ull r; asm("mul.rn.f32x2 %0, %1, %2;" : "=l"(r) : "l"(a), "l"(b)); return r;
}

// ============================================================================
// Kernel 1: QKV projections. grid (128, 3), block 256. smem = 96 KB dynamic.
// proj 0/1 (q,k) write transposed scratch; proj 2 (v) writes row-major.
// ============================================================================
__global__ __launch_bounds__(256) void qkv_kernel(
    const float* __restrict__ H, const float* __restrict__ Wq,
    const float* __restrict__ Wk, const float* __restrict__ Wv)
{
    extern __shared__ float sm[];
    float* sA = sm;            // 64 x 128 H tile
    float* sW = sm + 64 * DD;  // 128 x 128 weight

    const int t = threadIdx.x;
    const int rb = blockIdx.x * 64;
    const int proj = blockIdx.y;
    const float* W = (proj == 0) ? Wq : (proj == 1) ? Wk : Wv;

    {
        const float4* src = (const float4*)(H + (size_t)rb * DD);
        float4* dst = (float4*)sA;
        #pragma unroll
        for (int i = t; i < 64 * DD / 4; i += 256) dst[i] = src[i];
        const float4* srcW = (const float4*)W;
        float4* dstW = (float4*)sW;
        #pragma unroll
        for (int i = t; i < DD * DD / 4; i += 256) dstW[i] = srcW[i];
    }
    __syncthreads();

    const int ty = t >> 4, tx = t & 15;
    const int i0 = ty * 4;
    float acc[4][8];
    #pragma unroll
    for (int a = 0; a < 4; a++)
        #pragma unroll
        for (int b = 0; b < 8; b++) acc[a][b] = 0.f;

    #pragma unroll 4
    for (int k = 0; k < DD; k++) {
        float4 w0 = *(const float4*)&sW[k * DD + tx * 4];
        float4 w1 = *(const float4*)&sW[k * DD + 64 + tx * 4];
        #pragma unroll
        for (int ii = 0; ii < 4; ii++) {
            float a = sA[(i0 + ii) * DD + k];
            acc[ii][0] = fmaf(a, w0.x, acc[ii][0]);
            acc[ii][1] = fmaf(a, w0.y, acc[ii][1]);
            acc[ii][2] = fmaf(a, w0.z, acc[ii][2]);
            acc[ii][3] = fmaf(a, w0.w, acc[ii][3]);
            acc[ii][4] = fmaf(a, w1.x, acc[ii][4]);
            acc[ii][5] = fmaf(a, w1.y, acc[ii][5]);
            acc[ii][6] = fmaf(a, w1.z, acc[ii][6]);
            acc[ii][7] = fmaf(a, w1.w, acc[ii][7]);
        }
    }

    if (proj == 2) {
        #pragma unroll
        for (int ii = 0; ii < 4; ii++) {
            float4 o0 = make_float4(acc[ii][0], acc[ii][1], acc[ii][2], acc[ii][3]);
            float4 o1 = make_float4(acc[ii][4], acc[ii][5], acc[ii][6], acc[ii][7]);
            *(float4*)&g_v[(size_t)(rb + i0 + ii) * DD + tx * 4] = o0;
            *(float4*)&g_v[(size_t)(rb + i0 + ii) * DD + 64 + tx * 4] = o1;
        }
    } else {
        float* dst = proj ? g_kt : g_qt;
        #pragma unroll
        for (int ii = 0; ii < 4; ii++) {
            #pragma unroll
            for (int c = 0; c < 8; c++) {
                int col = (c < 4) ? (tx * 4 + c) : (64 + tx * 4 + (c - 4));
                dst[(size_t)col * NN + rb + i0 + ii] = acc[ii][c];
            }
        }
    }
}

// ============================================================================
// Kernel 2: flash attention with adjacency mask. grid 128, block 256.
// Br = Bc = 64. All mainloop math is packed f32x2 (FFMA2).
// smem: Qdup[128][128] 64K | Kt[128][64] 32K | V[64][128] 32K | Pdup[64][128] 32K
//  -> 160 KB dynamic, 1 CTA/SM.
// Duplicated layouts pre-pack the broadcast operand of each outer product.
// ============================================================================
__global__ __launch_bounds__(256) void attn_kernel(const int* __restrict__ adj)
{
    extern __shared__ float sm[];
    float* sQd = sm;                 // [128][128]: sQd[d][2i]=sQd[d][2i+1]=q[i][d]
    float* sKt = sQd + DD * 128;     // [128][64]:  sKt[d][j]=k[j][d]
    float* sV  = sKt + DD * 64;      // [64][128]
    float* sPd = sV + 64 * DD;       // [64][128]: p duplicated over j
    ull* sPd64 = (ull*)sPd;

    const int t = threadIdx.x;
    const int ty = t >> 4, tx = t & 15;
    const int qb = blockIdx.x * 64;
    const int i0 = ty * 4;           // query rows owned by this thread
    const int j0 = tx * 4;           // key cols owned within S tile

    // Fill duplicated-Q tile (coalesced gmem read; one-time 2-way STS)
    for (int idx = t; idx < DD * 64; idx += 256) {
        int d = idx >> 6, i = idx & 63;
        float v = g_qt[(size_t)d * NN + qb + i];
        sQd[d * 128 + 2 * i]     = v;
        sQd[d * 128 + 2 * i + 1] = v;
    }

    float m[4], l[4];
    ull O2[4][4];
    #pragma unroll
    for (int ii = 0; ii < 4; ii++) {
        m[ii] = -1e30f; l[ii] = 0.f;
        #pragma unroll
        for (int c = 0; c < 4; c++) O2[ii][c] = 0ull;
    }

    for (int kb = 0; kb < NN / 64; kb++) {
        // Prefetch adjacency (HBM, ~600 cyc) — hidden behind tile load + S GEMM
        int4 av[4];
        #pragma unroll
        for (int ii = 0; ii < 4; ii++)
            av[ii] = *(const int4*)(adj + (size_t)(qb + i0 + ii) * NN + kb * 64 + j0);

        __syncthreads();   // prev PV reads done before overwriting Kt/V
        #pragma unroll
        for (int idx = t; idx < DD * 64 / 4; idx += 256) {
            int d = idx >> 4, i4 = (idx & 15) << 2;
            *(float4*)&sKt[d * 64 + i4] =
                *(const float4*)&g_kt[(size_t)d * NN + kb * 64 + i4];
        }
        #pragma unroll
        for (int idx = t; idx < 64 * DD / 4; idx += 256) {
            int j = idx >> 5, d4 = (idx & 31) << 2;
            *(float4*)&sV[j * DD + d4] =
                *(const float4*)&g_v[(size_t)(kb * 64 + j) * DD + d4];
        }
        __syncthreads();

        // ---- S = Q Kt : 4x4 micro-tile, all FFMA2 ----
        ull s2[4][2];
        #pragma unroll
        for (int ii = 0; ii < 4; ii++) { s2[ii][0] = 0ull; s2[ii][1] = 0ull; }

        #pragma unroll 4
        for (int d = 0; d < DD; d++) {
            ulonglong2 a0 = *(const ulonglong2*)&sQd[d * 128 + 2 * i0];      // (qi0,qi0),(qi1,qi1)
            ulonglong2 a1 = *(const ulonglong2*)&sQd[d * 128 + 2 * i0 + 4];  // (qi2,qi2),(qi3,qi3)
            ulonglong2 bb = *(const ulonglong2*)&sKt[d * 64 + j0];           // (kj0,kj1),(kj2,kj3)
            fma2(s2[0][0], a0.x, bb.x); fma2(s2[0][1], a0.x, bb.y);
            fma2(s2[1][0], a0.y, bb.x); fma2(s2[1][1], a0.y, bb.y);
            fma2(s2[2][0], a1.x, bb.x); fma2(s2[2][1], a1.x, bb.y);
            fma2(s2[3][0], a1.y, bb.x); fma2(s2[3][1], a1.y, bb.y);
        }

        // ---- mask + online softmax (row group = half-warp of 16 lanes) ----
        #pragma unroll
        for (int ii = 0; ii < 4; ii++) {
            float s0, s1, s2f, s3;
            upk2(s2[ii][0], s0, s1);
            upk2(s2[ii][1], s2f, s3);
            if (av[ii].x <= 0) s0  -= 1e6f;
            if (av[ii].y <= 0) s1  -= 1e6f;
            if (av[ii].z <= 0) s2f -= 1e6f;
            if (av[ii].w <= 0) s3  -= 1e6f;
            float rmax = fmaxf(fmaxf(s0, s1), fmaxf(s2f, s3));
            #pragma unroll
            for (int w = 1; w < 16; w <<= 1)
                rmax = fmaxf(rmax, __shfl_xor_sync(0xffffffffu, rmax, w, 16));
            float mn = fmaxf(m[ii], rmax);
            float p0 = __expf(s0 - mn),  p1 = __expf(s1 - mn);
            float p2 = __expf(s2f - mn), p3 = __expf(s3 - mn);
            float rsum = (p0 + p1) + (p2 + p3);
            #pragma unroll
            for (int w = 1; w < 16; w <<= 1)
                rsum += __shfl_xor_sync(0xffffffffu, rsum, w, 16);
            float sc = __expf(m[ii] - mn);
            l[ii] = l[ii] * sc + rsum;
            m[ii] = mn;
            ull sc2 = pk2(sc, sc);
            #pragma unroll
            for (int c = 0; c < 4; c++) O2[ii][c] = mul2(O2[ii][c], sc2);
            sPd64[(i0 + ii) * 64 + j0 + 0] = pk2(p0, p0);
            sPd64[(i0 + ii) * 64 + j0 + 1] = pk2(p1, p1);
            sPd64[(i0 + ii) * 64 + j0 + 2] = pk2(p2, p2);
            sPd64[(i0 + ii) * 64 + j0 + 3] = pk2(p3, p3);
        }
        __syncthreads();

        // ---- O += P V : cols {tx*4..+3} and {64+tx*4..+3} (conflict-free LDS) ----
        #pragma unroll 2
        for (int j = 0; j < 64; j++) {
            ulonglong2 v0 = *(const ulonglong2*)&sV[j * DD + tx * 4];
            ulonglong2 v1 = *(const ulonglong2*)&sV[j * DD + 64 + tx * 4];
            #pragma unroll
            for (int ii = 0; ii < 4; ii++) {
                ull p = sPd64[(i0 + ii) * 64 + j];
                fma2(O2[ii][0], p, v0.x);
                fma2(O2[ii][1], p, v0.y);
                fma2(O2[ii][2], p, v1.x);
                fma2(O2[ii][3], p, v1.y);
            }
        }
    }

    // epilogue: normalize and write M row-major
    #pragma unroll
    for (int ii = 0; ii < 4; ii++) {
        float inv = 1.0f / l[ii];
        float o[8];
        upk2(O2[ii][0], o[0], o[1]);
        upk2(O2[ii][1], o[2], o[3]);
        upk2(O2[ii][2], o[4], o[5]);
        upk2(O2[ii][3], o[6], o[7]);
        float4 w0 = make_float4(o[0]*inv, o[1]*inv, o[2]*inv, o[3]*inv);
        float4 w1 = make_float4(o[4]*inv, o[5]*inv, o[6]*inv, o[7]*inv);
        *(float4*)&g_m[(size_t)(qb + i0 + ii) * DD + tx * 4] = w0;
        *(float4*)&g_m[(size_t)(qb + i0 + ii) * DD + 64 + tx * 4] = w1;
    }
}

// ============================================================================
// Kernel 3: MLP  out = relu(relu(M@W1+b1)@W2+b2). grid 128, block 256, 128 KB.
// ============================================================================
__global__ __launch_bounds__(256) void mlp_kernel(
    const float* __restrict__ W1, const float* __restrict__ b1,
    const float* __restrict__ W2, const float* __restrict__ b2,
    float* __restrict__ out)
{
    extern __shared__ float sm[];
    float* sM = sm;             // 64 x 128
    float* sH = sM + 64 * DD;   // 64 x 128
    float* sW = sH + 64 * DD;   // 128 x 128
    const int t = threadIdx.x;
    const int rb = blockIdx.x * 64;
    const int ty = t >> 4, tx = t & 15;
    const int i0 = ty * 4;

    {
        const float4* src = (const float4*)(g_m + (size_t)rb * DD);
        float4* dst = (float4*)sM;
        #pragma unroll
        for (int i = t; i < 64 * DD / 4; i += 256) dst[i] = src[i];
        const float4* srcW = (const float4*)W1;
        float4* dstW = (float4*)sW;
        #pragma unroll
        for (int i = t; i < DD * DD / 4; i += 256) dstW[i] = srcW[i];
    }
    __syncthreads();

    float4 bb0 = *(const float4*)&b1[tx * 4];
    float4 bb1 = *(const float4*)&b1[64 + tx * 4];

    float acc[4][8];
    #pragma unroll
    for (int a = 0; a < 4; a++)
        #pragma unroll
        for (int b = 0; b < 8; b++) acc[a][b] = 0.f;

    #pragma unroll 4
    for (int k = 0; k < DD; k++) {
        float4 w0 = *(const float4*)&sW[k * DD + tx * 4];
        float4 w1 = *(const float4*)&sW[k * DD + 64 + tx * 4];
        #pragma unroll
        for (int ii = 0; ii < 4; ii++) {
            float a = sM[(i0 + ii) * DD + k];
            acc[ii][0] = fmaf(a, w0.x, acc[ii][0]);
            acc[ii][1] = fmaf(a, w0.y, acc[ii][1]);
            acc[ii][2] = fmaf(a, w0.z, acc[ii][2]);
            acc[ii][3] = fmaf(a, w0.w, acc[ii][3]);
            acc[ii][4] = fmaf(a, w1.x, acc[ii][4]);
            acc[ii][5] = fmaf(a, w1.y, acc[ii][5]);
            acc[ii][6] = fmaf(a, w1.z, acc[ii][6]);
            acc[ii][7] = fmaf(a, w1.w, acc[ii][7]);
        }
    }
    #pragma unroll
    for (int ii = 0; ii < 4; ii++) {
        sH[(i0 + ii) * DD + tx * 4 + 0] = fmaxf(acc[ii][0] + bb0.x, 0.f);
        sH[(i0 + ii) * DD + tx * 4 + 1] = fmaxf(acc[ii][1] + bb0.y, 0.f);
        sH[(i0 + ii) * DD + tx * 4 + 2] = fmaxf(acc[ii][2] + bb0.z, 0.f);
        sH[(i0 + ii) * DD + tx * 4 + 3] = fmaxf(acc[ii][3] + bb0.w, 0.f);
        sH[(i0 + ii) * DD + 64 + tx * 4 + 0] = fmaxf(acc[ii][4] + bb1.x, 0.f);
        sH[(i0 + ii) * DD + 64 + tx * 4 + 1] = fmaxf(acc[ii][5] + bb1.y, 0.f);
        sH[(i0 + ii) * DD + 64 + tx * 4 + 2] = fmaxf(acc[ii][6] + bb1.z, 0.f);
        sH[(i0 + ii) * DD + 64 + tx * 4 + 3] = fmaxf(acc[ii][7] + bb1.w, 0.f);
    }
    __syncthreads();   // all W1 reads done

    {
        const float4* srcW = (const float4*)W2;
        float4* dstW = (float4*)sW;
        #pragma unroll
        for (int i = t; i < DD * DD / 4; i += 256) dstW[i] = srcW[i];
    }
    __syncthreads();

    bb0 = *(const float4*)&b2[tx * 4];
    bb1 = *(const float4*)&b2[64 + tx * 4];
    #pragma unroll
    for (int a = 0; a < 4; a++)
        #pragma unroll
        for (int b = 0; b < 8; b++) acc[a][b] = 0.f;

    #pragma unroll 4
    for (int k = 0; k < DD; k++) {
        float4 w0 = *(const float4*)&sW[k * DD + tx * 4];
        float4 w1 = *(const float4*)&sW[k * DD + 64 + tx * 4];
        #pragma unroll
        for (int ii = 0; ii < 4; ii++) {
            float a = sH[(i0 + ii) * DD + k];
            acc[ii][0] = fmaf(a, w0.x, acc[ii][0]);
            acc[ii][1] = fmaf(a, w0.y, acc[ii][1]);
            acc[ii][2] = fmaf(a, w0.z, acc[ii][2]);
            acc[ii][3] = fmaf(a, w0.w, acc[ii][3]);
            acc[ii][4] = fmaf(a, w1.x, acc[ii][4]);
            acc[ii][5] = fmaf(a, w1.y, acc[ii][5]);
            acc[ii][6] = fmaf(a, w1.z, acc[ii][6]);
            acc[ii][7] = fmaf(a, w1.w, acc[ii][7]);
        }
    }
    #pragma unroll
    for (int ii = 0; ii < 4; ii++) {
        float4 o0 = make_float4(fmaxf(acc[ii][0] + bb0.x, 0.f),
                                fmaxf(acc[ii][1] + bb0.y, 0.f),
                                fmaxf(acc[ii][2] + bb0.z, 0.f),
                                fmaxf(acc[ii][3] + bb0.w, 0.f));
        float4 o1 = make_float4(fmaxf(acc[ii][4] + bb1.x, 0.f),
                                fmaxf(acc[ii][5] + bb1.y, 0.f),
                                fmaxf(acc[ii][6] + bb1.z, 0.f),
                                fmaxf(acc[ii][7] + bb1.w, 0.f));
        *(float4*)&out[(size_t)(rb + i0 + ii) * DD + tx * 4] = o0;
        *(float4*)&out[(size_t)(rb + i0 + ii) * DD + 64 + tx * 4] = o1;
    }
}

// ============================================================================
extern "C" void kernel_launch(void* const* d_in, const int* in_sizes, int n_in,
                              void* d_out, int out_size) {
    const float* H  = (const float*)d_in[0];
    const int*   adj= (const int*)  d_in[1];
    const float* Wq = (const float*)d_in[2];
    const float* Wk = (const float*)d_in[3];
    const float* Wv = (const float*)d_in[4];
    const float* W1 = (const float*)d_in[5];
    const float* b1 = (const float*)d_in[6];
    const float* W2 = (const float*)d_in[7];
    const float* b2 = (const float*)d_in[8];
    float* out = (float*)d_out;

    cudaFuncSetAttribute(qkv_kernel,  cudaFuncAttributeMaxDynamicSharedMemorySize, 96 * 1024);
    cudaFuncSetAttribute(attn_kernel, cudaFuncAttributeMaxDynamicSharedMemorySize, 160 * 1024);
    cudaFuncSetAttribute(mlp_kernel,  cudaFuncAttributeMaxDynamicSharedMemorySize, 128 * 1024);

    qkv_kernel<<<dim3(NN / 64, 3), 256, 96 * 1024>>>(H, Wq, Wk, Wv);
    attn_kernel<<<NN / 64, 256, 160 * 1024>>>(adj);
    mlp_kernel<<<NN / 64, 256, 128 * 1024>>>(W1, b1, W2, b2, out);
}